// round 6
// baseline (speedup 1.0000x reference)
#include <cuda_runtime.h>
#include <cuda_fp8.h>
#include <cuda_fp16.h>
#include <cstdint>

#define NROW 2048
#define NCOL 4096
#define NBATCH 4
#define KMAX 256
#define CUT 30.0f

// ---------------- device scratch ----------
__device__ float    g_q   [(size_t)NBATCH * NROW * NCOL];            // 128 MB fp32
__device__ __align__(16) uint8_t g_q8[(size_t)NBATCH * NROW * NCOL]; // 32 MB e4m3
__device__ __align__(16) __half  g_e16[(size_t)NBATCH * NROW * NROW];// 32 MB fp16
__device__ uint32_t g_rowmin_u[NBATCH * NROW];
__device__ int      g_cnt [NBATCH * NROW];
__device__ int      g_sidx[(size_t)NBATCH * NROW * KMAX];
__device__ float    g_sw  [(size_t)NBATCH * NROW * KMAX];

__device__ __forceinline__ uint32_t fkey(float f) {
    uint32_t u = __float_as_uint(f);
    return (u & 0x80000000u) ? ~u : (u | 0x80000000u);
}
__device__ __forceinline__ float fdecode(uint32_t k) {
    return (k & 0x80000000u) ? __uint_as_float(k ^ 0x80000000u) : __uint_as_float(~k);
}

// ---------------- kernel 1: space_to_channel pack + fp8 quantize -----------
__global__ void __launch_bounds__(256) pack_kernel(const float* __restrict__ x) {
    unsigned tid = blockIdx.x * 256u + threadIdx.x;
    if (tid < NBATCH * NROW) g_rowmin_u[tid] = 0xFFFFFFFFu;
    int d4 = tid & 15;
    int h  = (tid >> 4) & 63;
    int w  = (tid >> 10) & 63;
    int c  = (tid >> 16) & 31;
    int b  = tid >> 21;
    float4 v = reinterpret_cast<const float4*>(x)[tid];
    int n   = ((w >> 2) << 8) + (((w & 3) << 2) + (h >> 4)) * 16 + d4;
    int chb = ((h & 15) << 7) + c;
    size_t base = ((size_t)(b * NROW + chb)) * NCOL + n;
    float vv[4] = {v.x, v.y, v.z, v.w};
#pragma unroll
    for (int j = 0; j < 4; j++) {
        size_t idx = base + (size_t)j * 32 * NCOL;
        float f = vv[j];
        g_q[idx] = f;
        g_q8[idx] = (uint8_t)__nv_cvt_float_to_fp8(f, __NV_SATFINITE, __NV_E4M3);
    }
}

// ---------------- kernel 2: approx Gram (e4m3, fp32 accum) -----------------
#define MMA_FP8(cacc, aa, bb) \
    asm volatile( \
        "mma.sync.aligned.m16n8k32.row.col.f32.e4m3.e4m3.f32 " \
        "{%0,%1,%2,%3},{%4,%5,%6,%7},{%8,%9},{%0,%1,%2,%3};\n" \
        : "+f"(cacc[0]), "+f"(cacc[1]), "+f"(cacc[2]), "+f"(cacc[3]) \
        : "r"(aa[0]), "r"(aa[1]), "r"(aa[2]), "r"(aa[3]), "r"(bb[0]), "r"(bb[1]))

__global__ void __launch_bounds__(256) gram_kernel() {
    int b = blockIdx.y;
    int t = blockIdx.x;
    int ti = 0;
    while (t >= 16 - ti) { t -= 16 - ti; ti++; }
    int tj = ti + t;                                  // ti <= tj

    extern __shared__ unsigned char smem_raw[];
    uint8_t* sm = (uint8_t*)smem_raw;
    const int ARR = 128 * 80;
    const int STG = 2 * ARR;

    int tid  = threadIdx.x;
    int lane = tid & 31;
    int warp = tid >> 5;
    int wm = warp >> 2;
    int wn = warp & 3;

    size_t rowA = (size_t)(b * NROW + ti * 128);
    size_t rowB = (size_t)(b * NROW + tj * 128);

    auto load_stage = [&](int stage, int chunk) {
#pragma unroll
        for (int it = 0; it < 4; it++) {
            int u   = it * 256 + tid;
            int arr = u >> 9;
            int rr  = (u >> 2) & 127;
            int seg = (u & 3);
            size_t row = (arr ? rowB : rowA) + rr;
            const uint8_t* gp = g_q8 + row * NCOL + chunk * 64 + seg * 16;
            unsigned sp = (unsigned)__cvta_generic_to_shared(
                sm + stage * STG + arr * ARR + rr * 80 + seg * 16);
            asm volatile("cp.async.cg.shared.global [%0], [%1], 16;\n"
                         :: "r"(sp), "l"(gp));
        }
    };

    float acc[4][4][4];
#pragma unroll
    for (int a = 0; a < 4; a++)
#pragma unroll
        for (int bq = 0; bq < 4; bq++)
#pragma unroll
            for (int r = 0; r < 4; r++) acc[a][bq][r] = 0.f;

    const int KT = NCOL / 64;
    load_stage(0, 0);
    asm volatile("cp.async.commit_group;\n");
    load_stage(1, 1);
    asm volatile("cp.async.commit_group;\n");

    for (int kt = 0; kt < KT; kt++) {
        if (kt + 2 < KT) {
            load_stage((kt + 2) % 3, kt + 2);
            asm volatile("cp.async.commit_group;\n");
            asm volatile("cp.async.wait_group 2;\n");
        } else if (kt + 1 < KT) {
            asm volatile("cp.async.wait_group 1;\n");
        } else {
            asm volatile("cp.async.wait_group 0;\n");
        }
        __syncthreads();
        const uint8_t* st = sm + (kt % 3) * STG;

#pragma unroll
        for (int ks = 0; ks < 2; ks++) {
            unsigned ahi[4][4], bhi[4][2];
#pragma unroll
            for (int mt = 0; mt < 4; mt++) {
                int r    = wm * 64 + mt * 16 + (lane & 15);
                int coff = ks * 32 + ((lane >> 4) << 4);
                unsigned ah = (unsigned)__cvta_generic_to_shared(st + 0 * ARR + r * 80 + coff);
                asm volatile("ldmatrix.sync.aligned.m8n8.x4.shared.b16 {%0,%1,%2,%3}, [%4];\n"
                    : "=r"(ahi[mt][0]), "=r"(ahi[mt][1]), "=r"(ahi[mt][2]), "=r"(ahi[mt][3])
                    : "r"(ah));
            }
#pragma unroll
            for (int nt = 0; nt < 4; nt++) {
                int lb   = lane & 15;
                int r    = wn * 32 + nt * 8 + (lb & 7);
                int coff = ks * 32 + (((lb >> 3) & 1) << 4);
                unsigned bh = (unsigned)__cvta_generic_to_shared(st + 1 * ARR + r * 80 + coff);
                asm volatile("ldmatrix.sync.aligned.m8n8.x2.shared.b16 {%0,%1}, [%2];\n"
                    : "=r"(bhi[nt][0]), "=r"(bhi[nt][1]) : "r"(bh));
            }
#pragma unroll
            for (int mt = 0; mt < 4; mt++)
#pragma unroll
                for (int nt = 0; nt < 4; nt++)
                    MMA_FP8(acc[mt][nt], ahi[mt], bhi[nt]);
        }
        __syncthreads();
    }

    // epilogue: accumulators -> smem fp32 tile
    float* sF = (float*)smem_raw;    // 128 x 129
    int lr = lane >> 2, lc = (lane & 3) * 2;
#pragma unroll
    for (int mt = 0; mt < 4; mt++)
#pragma unroll
        for (int nt = 0; nt < 4; nt++) {
            int r = wm * 64 + mt * 16 + lr;
            int c = wn * 32 + nt * 8 + lc;
            sF[r * 129 + c]           = acc[mt][nt][0];
            sF[r * 129 + c + 1]       = acc[mt][nt][1];
            sF[(r + 8) * 129 + c]     = acc[mt][nt][2];
            sF[(r + 8) * 129 + c + 1] = acc[mt][nt][3];
        }
    __syncthreads();

    // per-row / per-col tile minima -> global atomicMin
    if (tid < 128) {
        float mv = 3.4e38f;
        const float* rp = sF + tid * 129;
#pragma unroll 8
        for (int c = 0; c < 128; c++) mv = fminf(mv, rp[c]);
        atomicMin(&g_rowmin_u[b * NROW + ti * 128 + tid], fkey(mv));
    } else if (ti != tj) {
        int c = tid - 128;
        float mv = 3.4e38f;
#pragma unroll 8
        for (int r = 0; r < 128; r++) mv = fminf(mv, sF[r * 129 + c]);
        atomicMin(&g_rowmin_u[b * NROW + tj * 128 + c], fkey(mv));
    }

    // fp16 energy store (+ mirror)
    size_t ebase = (size_t)b * NROW * NROW;
    for (int u = tid; u < 8192; u += 256) {
        int r = u >> 6, c2 = u & 63;
        __half2 hv = __floats2half2_rn(sF[r * 129 + 2 * c2], sF[r * 129 + 2 * c2 + 1]);
        *reinterpret_cast<__half2*>(
            g_e16 + ebase + (size_t)(ti * 128 + r) * NROW + tj * 128 + 2 * c2) = hv;
    }
    if (ti != tj) {
        for (int u = tid; u < 8192; u += 256) {
            int r = u >> 6, c2 = u & 63;
            __half2 hv = __floats2half2_rn(sF[(2 * c2) * 129 + r], sF[(2 * c2 + 1) * 129 + r]);
            *reinterpret_cast<__half2*>(
                g_e16 + ebase + (size_t)(tj * 128 + r) * NROW + ti * 128 + 2 * c2) = hv;
        }
    }
}

// ------- kernel 3: fused candidate scan + exact fp32 refine + softmax ------
// 512 threads; refine dots split into (candidate x quarter-row) work items
// so all 16 warps stay busy even with ~3 candidates.
__global__ void __launch_bounds__(512) candref_kernel() {
    int row = blockIdx.x;                              // b*NROW + r
    int b = row >> 11;
    int t = threadIdx.x;
    int lane = t & 31, warp = t >> 5;
    __shared__ float4 qi4[NCOL / 4];
    __shared__ int   cidx[KMAX];
    __shared__ float ex[KMAX];
    __shared__ int scnt;

    if (t == 0) scnt = 0;
    if (t < KMAX) ex[t] = 0.f;
    const float4* qrow4 = reinterpret_cast<const float4*>(g_q + (size_t)row * NCOL);
#pragma unroll
    for (int u = 0; u < 2; u++) qi4[t + u * 512] = qrow4[t + u * 512];
    float thr = fdecode(g_rowmin_u[row]) + CUT;
    __syncthreads();

    // candidate collect: 8B load = 4 halves per thread
    uint2 ev = reinterpret_cast<const uint2*>(g_e16 + (size_t)row * NROW)[t];
    {
        uint32_t ww[2] = {ev.x, ev.y};
#pragma unroll
        for (int p = 0; p < 2; p++) {
            __half2 h2 = *reinterpret_cast<__half2*>(&ww[p]);
            float e0 = __low2float(h2), e1 = __high2float(h2);
            if (e0 < thr) { int pos = atomicAdd(&scnt, 1); if (pos < KMAX) cidx[pos] = t * 4 + 2 * p; }
            if (e1 < thr) { int pos = atomicAdd(&scnt, 1); if (pos < KMAX) cidx[pos] = t * 4 + 2 * p + 1; }
        }
    }
    __syncthreads();
    int cnt = (scnt > KMAX) ? KMAX : scnt;

    // exact fp32 dots: work item = (candidate, quarter-row of 1024 floats)
    for (int i = warp; i < cnt * 4; i += 16) {
        int c = i >> 2, qtr = i & 3;
        int j = cidx[c];
        const float4* qj4 = reinterpret_cast<const float4*>(
            g_q + ((size_t)(b * NROW + j)) * NCOL) + qtr * 256;
        const float4* qa = qi4 + qtr * 256;
        float s = 0.f;
#pragma unroll
        for (int u = 0; u < 8; u++) {
            float4 a = qa[lane + u * 32];
            float4 bv = __ldg(&qj4[lane + u * 32]);
            s += a.x * bv.x + a.y * bv.y + a.z * bv.z + a.w * bv.w;
        }
#pragma unroll
        for (int o = 16; o > 0; o >>= 1) s += __shfl_xor_sync(0xFFFFFFFFu, s, o);
        if (lane == 0) atomicAdd(&ex[c], s);
    }
    __syncthreads();

    if (t == 0) {
        float m = 3.4e38f;
        for (int c = 0; c < cnt; c++) m = fminf(m, ex[c]);
        float Z = 0.f;
        for (int c = 0; c < cnt; c++) { float w = __expf(m - ex[c]); ex[c] = w; Z += w; }
        float inv = 1.0f / Z;
        int newc = 0;
        for (int c = 0; c < cnt; c++) {
            float w = ex[c] * inv;
            if (w > 3e-7f) {
                g_sidx[(size_t)row * KMAX + newc] = cidx[c];
                g_sw  [(size_t)row * KMAX + newc] = w;
                newc++;
            }
        }
        g_cnt[row] = newc;
    }
}

// ---------------- kernel 4: sparse AV + gamma*out + y + channel_to_space ---
__global__ void __launch_bounds__(256) av_kernel(const float* __restrict__ gamma_ptr,
                                                 float* __restrict__ out) {
    int blk = blockIdx.x;               // 8192 blocks
    int it = blk & 3;
    int cs = (blk >> 2) & 31;
    int e2 = (blk >> 7) & 15;
    int b  = blk >> 11;
    float gamma = __ldg(gamma_ptr);
    int t = threadIdx.x;

    __shared__ int   s_idx[4][KMAX];
    __shared__ float s_w[4][KMAX];
    __shared__ int   s_cnt[4];

    if (t < 4) s_cnt[t] = g_cnt[b * NROW + e2 * 128 + t * 32 + cs];
    __syncthreads();
#pragma unroll
    for (int e1 = 0; e1 < 4; e1++) {
        size_t lbase = ((size_t)(b * NROW + e2 * 128 + e1 * 32 + cs)) * KMAX;
        for (int k = t; k < s_cnt[e1]; k += 256) {
            s_idx[e1][k] = g_sidx[lbase + k];
            s_w[e1][k]   = g_sw[lbase + k];
        }
    }
    __syncthreads();

    const float4* qb4 = reinterpret_cast<const float4*>(g_q + (size_t)b * NROW * NCOL);
    size_t obase = ((size_t)(b * 32 + cs)) * 64 * 64 * 64;
    int wq = e2 >> 2;
    int hq = (e2 & 3) * 16;

    int f = it * 256 + t;                      // float4 column 0..1023
    float res[4][4];
#pragma unroll
    for (int e1 = 0; e1 < 4; e1++) {
        int rl = e2 * 128 + e1 * 32 + cs;
        int cnt = s_cnt[e1];
        float a0 = 0.f, a1 = 0.f, a2 = 0.f, a3 = 0.f;
        for (int k = 0; k < cnt; k++) {
            float4 v = __ldg(&qb4[(size_t)s_idx[e1][k] * 1024 + f]);
            float w = s_w[e1][k];
            a0 += w * v.x; a1 += w * v.y; a2 += w * v.z; a3 += w * v.w;
        }
        float4 y = __ldg(&qb4[(size_t)rl * 1024 + f]);
        res[e1][0] = gamma * a0 + y.x;
        res[e1][1] = gamma * a1 + y.y;
        res[e1][2] = gamma * a2 + y.z;
        res[e1][3] = gamma * a3 + y.w;
    }
    int n0 = f * 4;
    int wd = n0 >> 8, hd = (n0 >> 4) & 15, dd0 = n0 & 15;
    int Wn = wd * 4 + wq;
    int Hn = hq + hd;
    size_t oi = obase + (size_t)Wn * 4096 + (size_t)Hn * 64 + dd0 * 4;
#pragma unroll
    for (int nn = 0; nn < 4; nn++) {
        *reinterpret_cast<float4*>(out + oi + nn * 4) =
            make_float4(res[0][nn], res[1][nn], res[2][nn], res[3][nn]);
    }
}

// ---------------- launch ---------------------------------------------------
extern "C" void kernel_launch(void* const* d_in, const int* in_sizes, int n_in,
                              void* d_out, int out_size) {
    const float* x     = (const float*)d_in[0];
    const float* gamma = (const float*)d_in[1];
    float* out = (float*)d_out;

    pack_kernel<<<32768, 256>>>(x);

    cudaFuncSetAttribute(gram_kernel, cudaFuncAttributeMaxDynamicSharedMemorySize, 67584);
    gram_kernel<<<dim3(136, 4), 256, 67584>>>();

    candref_kernel<<<NBATCH * NROW, 512>>>();

    av_kernel<<<8192, 256>>>(gamma, out);
}

// round 7
// speedup vs baseline: 1.0784x; 1.0784x over previous
#include <cuda_runtime.h>
#include <cuda_fp8.h>
#include <cuda_fp16.h>
#include <cstdint>

#define NROW 2048
#define NCOL 4096
#define NBATCH 4
#define CMAX 64
#define CUT 30.0f

// ---------------- device scratch ----------
__device__ float    g_q   [(size_t)NBATCH * NROW * NCOL];            // 128 MB fp32
__device__ __align__(16) uint8_t g_q8[(size_t)NBATCH * NROW * NCOL]; // 32 MB e4m3
__device__ __align__(16) __half  g_e16[(size_t)NBATCH * NROW * NROW];// 32 MB fp16
__device__ uint32_t g_rowmin_u[NBATCH * NROW];

__device__ __forceinline__ uint32_t fkey(float f) {
    uint32_t u = __float_as_uint(f);
    return (u & 0x80000000u) ? ~u : (u | 0x80000000u);
}
__device__ __forceinline__ float fdecode(uint32_t k) {
    return (k & 0x80000000u) ? __uint_as_float(k ^ 0x80000000u) : __uint_as_float(~k);
}

// ---------------- kernel 1: space_to_channel pack + fp8 quantize -----------
__global__ void __launch_bounds__(256) pack_kernel(const float* __restrict__ x) {
    unsigned tid = blockIdx.x * 256u + threadIdx.x;
    if (tid < NBATCH * NROW) g_rowmin_u[tid] = 0xFFFFFFFFu;
    int d4 = tid & 15;
    int h  = (tid >> 4) & 63;
    int w  = (tid >> 10) & 63;
    int c  = (tid >> 16) & 31;
    int b  = tid >> 21;
    float4 v = reinterpret_cast<const float4*>(x)[tid];
    int n   = ((w >> 2) << 8) + (((w & 3) << 2) + (h >> 4)) * 16 + d4;
    int chb = ((h & 15) << 7) + c;
    size_t base = ((size_t)(b * NROW + chb)) * NCOL + n;
    float vv[4] = {v.x, v.y, v.z, v.w};
#pragma unroll
    for (int j = 0; j < 4; j++) {
        size_t idx = base + (size_t)j * 32 * NCOL;
        float f = vv[j];
        g_q[idx] = f;
        g_q8[idx] = (uint8_t)__nv_cvt_float_to_fp8(f, __NV_SATFINITE, __NV_E4M3);
    }
}

// ---------------- kernel 2: approx Gram (e4m3, fp32 accum) -----------------
#define MMA_FP8(cacc, aa, bb) \
    asm volatile( \
        "mma.sync.aligned.m16n8k32.row.col.f32.e4m3.e4m3.f32 " \
        "{%0,%1,%2,%3},{%4,%5,%6,%7},{%8,%9},{%0,%1,%2,%3};\n" \
        : "+f"(cacc[0]), "+f"(cacc[1]), "+f"(cacc[2]), "+f"(cacc[3]) \
        : "r"(aa[0]), "r"(aa[1]), "r"(aa[2]), "r"(aa[3]), "r"(bb[0]), "r"(bb[1]))

__global__ void __launch_bounds__(256) gram_kernel() {
    int b = blockIdx.y;
    int t = blockIdx.x;
    int ti = 0;
    while (t >= 16 - ti) { t -= 16 - ti; ti++; }
    int tj = ti + t;                                  // ti <= tj

    extern __shared__ unsigned char smem_raw[];
    uint8_t* sm = (uint8_t*)smem_raw;
    const int ARR = 128 * 80;
    const int STG = 2 * ARR;

    int tid  = threadIdx.x;
    int lane = tid & 31;
    int warp = tid >> 5;
    int wm = warp >> 2;
    int wn = warp & 3;

    size_t rowA = (size_t)(b * NROW + ti * 128);
    size_t rowB = (size_t)(b * NROW + tj * 128);

    auto load_stage = [&](int stage, int chunk) {
#pragma unroll
        for (int it = 0; it < 4; it++) {
            int u   = it * 256 + tid;
            int arr = u >> 9;
            int rr  = (u >> 2) & 127;
            int seg = (u & 3);
            size_t row = (arr ? rowB : rowA) + rr;
            const uint8_t* gp = g_q8 + row * NCOL + chunk * 64 + seg * 16;
            unsigned sp = (unsigned)__cvta_generic_to_shared(
                sm + stage * STG + arr * ARR + rr * 80 + seg * 16);
            asm volatile("cp.async.cg.shared.global [%0], [%1], 16;\n"
                         :: "r"(sp), "l"(gp));
        }
    };

    float acc[4][4][4];
#pragma unroll
    for (int a = 0; a < 4; a++)
#pragma unroll
        for (int bq = 0; bq < 4; bq++)
#pragma unroll
            for (int r = 0; r < 4; r++) acc[a][bq][r] = 0.f;

    const int KT = NCOL / 64;
    load_stage(0, 0);
    asm volatile("cp.async.commit_group;\n");
    load_stage(1, 1);
    asm volatile("cp.async.commit_group;\n");

    for (int kt = 0; kt < KT; kt++) {
        if (kt + 2 < KT) {
            load_stage((kt + 2) % 3, kt + 2);
            asm volatile("cp.async.commit_group;\n");
            asm volatile("cp.async.wait_group 2;\n");
        } else if (kt + 1 < KT) {
            asm volatile("cp.async.wait_group 1;\n");
        } else {
            asm volatile("cp.async.wait_group 0;\n");
        }
        __syncthreads();
        const uint8_t* st = sm + (kt % 3) * STG;

#pragma unroll
        for (int ks = 0; ks < 2; ks++) {
            unsigned ahi[4][4], bhi[4][2];
#pragma unroll
            for (int mt = 0; mt < 4; mt++) {
                int r    = wm * 64 + mt * 16 + (lane & 15);
                int coff = ks * 32 + ((lane >> 4) << 4);
                unsigned ah = (unsigned)__cvta_generic_to_shared(st + 0 * ARR + r * 80 + coff);
                asm volatile("ldmatrix.sync.aligned.m8n8.x4.shared.b16 {%0,%1,%2,%3}, [%4];\n"
                    : "=r"(ahi[mt][0]), "=r"(ahi[mt][1]), "=r"(ahi[mt][2]), "=r"(ahi[mt][3])
                    : "r"(ah));
            }
#pragma unroll
            for (int nt = 0; nt < 4; nt++) {
                int lb   = lane & 15;
                int r    = wn * 32 + nt * 8 + (lb & 7);
                int coff = ks * 32 + (((lb >> 3) & 1) << 4);
                unsigned bh = (unsigned)__cvta_generic_to_shared(st + 1 * ARR + r * 80 + coff);
                asm volatile("ldmatrix.sync.aligned.m8n8.x2.shared.b16 {%0,%1}, [%2];\n"
                    : "=r"(bhi[nt][0]), "=r"(bhi[nt][1]) : "r"(bh));
            }
#pragma unroll
            for (int mt = 0; mt < 4; mt++)
#pragma unroll
                for (int nt = 0; nt < 4; nt++)
                    MMA_FP8(acc[mt][nt], ahi[mt], bhi[nt]);
        }
        __syncthreads();
    }

    // epilogue: accumulators -> smem fp32 tile
    float* sF = (float*)smem_raw;    // 128 x 129
    int lr = lane >> 2, lc = (lane & 3) * 2;
#pragma unroll
    for (int mt = 0; mt < 4; mt++)
#pragma unroll
        for (int nt = 0; nt < 4; nt++) {
            int r = wm * 64 + mt * 16 + lr;
            int c = wn * 32 + nt * 8 + lc;
            sF[r * 129 + c]           = acc[mt][nt][0];
            sF[r * 129 + c + 1]       = acc[mt][nt][1];
            sF[(r + 8) * 129 + c]     = acc[mt][nt][2];
            sF[(r + 8) * 129 + c + 1] = acc[mt][nt][3];
        }
    __syncthreads();

    // per-row / per-col tile minima -> global atomicMin
    if (tid < 128) {
        float mv = 3.4e38f;
        const float* rp = sF + tid * 129;
#pragma unroll 8
        for (int c = 0; c < 128; c++) mv = fminf(mv, rp[c]);
        atomicMin(&g_rowmin_u[b * NROW + ti * 128 + tid], fkey(mv));
    } else if (ti != tj) {
        int c = tid - 128;
        float mv = 3.4e38f;
#pragma unroll 8
        for (int r = 0; r < 128; r++) mv = fminf(mv, sF[r * 129 + c]);
        atomicMin(&g_rowmin_u[b * NROW + tj * 128 + c], fkey(mv));
    }

    // fp16 energy store (+ mirror)
    size_t ebase = (size_t)b * NROW * NROW;
    for (int u = tid; u < 8192; u += 256) {
        int r = u >> 6, c2 = u & 63;
        __half2 hv = __floats2half2_rn(sF[r * 129 + 2 * c2], sF[r * 129 + 2 * c2 + 1]);
        *reinterpret_cast<__half2*>(
            g_e16 + ebase + (size_t)(ti * 128 + r) * NROW + tj * 128 + 2 * c2) = hv;
    }
    if (ti != tj) {
        for (int u = tid; u < 8192; u += 256) {
            int r = u >> 6, c2 = u & 63;
            __half2 hv = __floats2half2_rn(sF[(2 * c2) * 129 + r], sF[(2 * c2 + 1) * 129 + r]);
            *reinterpret_cast<__half2*>(
                g_e16 + ebase + (size_t)(tj * 128 + r) * NROW + ti * 128 + 2 * c2) = hv;
        }
    }
}

// ---- kernel 3: FUSED scan + exact refine + softmax + sparse AV + c2s ------
// block = (b, e2, cs) -> 4 rows (e1 = 0..3). 512 threads.
__global__ void __launch_bounds__(512) fuse_kernel(const float* __restrict__ gamma_ptr,
                                                   float* __restrict__ out) {
    int blk = blockIdx.x;               // 2048 blocks
    int cs = blk & 31;
    int e2 = (blk >> 5) & 15;
    int b  = blk >> 9;
    int t = threadIdx.x;
    int lane = t & 31, warp = t >> 5;
    float gamma = __ldg(gamma_ptr);

    extern __shared__ float smem_f[];
    float4* qi4 = (float4*)smem_f;            // 4 rows x 1024 float4 = 64KB
    int*    cidx = (int*)(smem_f + 16384);    // 4 x CMAX
    float*  ex   = (float*)(cidx + 4 * CMAX); // 4 x CMAX
    int*    cnts = (int*)(ex + 4 * CMAX);     // 4
    int*    cum  = cnts + 4;                  // 5

    int rl[4];
#pragma unroll
    for (int e1 = 0; e1 < 4; e1++) rl[e1] = e2 * 128 + e1 * 32 + cs;

    if (t < 4) cnts[t] = 0;
    if (t < 4 * CMAX) ex[t] = 0.f;

    // load 4 qi rows into smem
    const float4* qb4 = reinterpret_cast<const float4*>(g_q + (size_t)b * NROW * NCOL);
#pragma unroll
    for (int e1 = 0; e1 < 4; e1++) {
        const float4* src = qb4 + (size_t)rl[e1] * 1024;
#pragma unroll
        for (int u = 0; u < 2; u++) qi4[e1 * 1024 + t + u * 512] = src[t + u * 512];
    }
    __syncthreads();

    // candidate collect from fp16 energy rows
#pragma unroll
    for (int e1 = 0; e1 < 4; e1++) {
        int grow = b * NROW + rl[e1];
        float thr = fdecode(g_rowmin_u[grow]) + CUT;
        uint2 ev = reinterpret_cast<const uint2*>(g_e16 + (size_t)grow * NROW)[t];
        uint32_t ww[2] = {ev.x, ev.y};
#pragma unroll
        for (int p = 0; p < 2; p++) {
            __half2 h2 = *reinterpret_cast<__half2*>(&ww[p]);
            float e0 = __low2float(h2), e1v = __high2float(h2);
            if (e0 < thr) {
                int pos = atomicAdd(&cnts[e1], 1);
                if (pos < CMAX) cidx[e1 * CMAX + pos] = t * 4 + 2 * p;
            }
            if (e1v < thr) {
                int pos = atomicAdd(&cnts[e1], 1);
                if (pos < CMAX) cidx[e1 * CMAX + pos] = t * 4 + 2 * p + 1;
            }
        }
    }
    __syncthreads();
    if (t == 0) {
        cum[0] = 0;
#pragma unroll
        for (int e1 = 0; e1 < 4; e1++) {
            int c = cnts[e1]; if (c > CMAX) c = CMAX;
            cnts[e1] = c;
            cum[e1 + 1] = cum[e1] + c;
        }
    }
    __syncthreads();

    // pass 1: exact fp32 dots; work item = (candidate, quarter-row)
    int total1 = cum[4] * 4;
    for (int i = warp; i < total1; i += 16) {
        int cq = i >> 2, qtr = i & 3;
        int e1 = 0;
        while (cq >= cum[e1 + 1]) e1++;
        int c = cq - cum[e1];
        int j = cidx[e1 * CMAX + c];
        const float4* qj4 = qb4 + (size_t)j * 1024 + qtr * 256;
        const float4* qa = qi4 + e1 * 1024 + qtr * 256;
        float s = 0.f;
#pragma unroll
        for (int u = 0; u < 8; u++) {
            float4 a = qa[lane + u * 32];
            float4 bv = __ldg(&qj4[lane + u * 32]);
            s += a.x * bv.x + a.y * bv.y + a.z * bv.z + a.w * bv.w;
        }
#pragma unroll
        for (int o = 16; o > 0; o >>= 1) s += __shfl_xor_sync(0xFFFFFFFFu, s, o);
        if (lane == 0) atomicAdd(&ex[e1 * CMAX + c], s);
    }
    __syncthreads();

    // softmax + prune (one thread per e1)
    if (t < 4) {
        int e1 = t, cnt = cnts[e1];
        float m = 3.4e38f;
        for (int c = 0; c < cnt; c++) m = fminf(m, ex[e1 * CMAX + c]);
        float Z = 0.f;
        for (int c = 0; c < cnt; c++) {
            float w = __expf(m - ex[e1 * CMAX + c]);
            ex[e1 * CMAX + c] = w; Z += w;
        }
        float inv = 1.0f / Z;
        int newc = 0;
        for (int c = 0; c < cnt; c++) {
            float w = ex[e1 * CMAX + c] * inv;
            if (w > 3e-7f) {
                cidx[e1 * CMAX + newc] = cidx[e1 * CMAX + c];
                ex[e1 * CMAX + newc] = w;
                newc++;
            }
        }
        cnts[e1] = newc;
    }
    __syncthreads();

    // pass 2: weighted combine (candidate rows L2-hot) + c2s output
    size_t obase = ((size_t)(b * 32 + cs)) * 64 * 64 * 64;
    int wq = e2 >> 2;
    int hq = (e2 & 3) * 16;

#pragma unroll
    for (int it = 0; it < 2; it++) {
        int f = it * 512 + t;                  // float4 column 0..1023
        float res[4][4];
#pragma unroll
        for (int e1 = 0; e1 < 4; e1++) {
            int cnt = cnts[e1];
            float a0 = 0.f, a1 = 0.f, a2 = 0.f, a3 = 0.f;
            for (int k = 0; k < cnt; k++) {
                float4 v = __ldg(&qb4[(size_t)cidx[e1 * CMAX + k] * 1024 + f]);
                float w = ex[e1 * CMAX + k];
                a0 += w * v.x; a1 += w * v.y; a2 += w * v.z; a3 += w * v.w;
            }
            float4 y = qi4[e1 * 1024 + f];
            res[e1][0] = gamma * a0 + y.x;
            res[e1][1] = gamma * a1 + y.y;
            res[e1][2] = gamma * a2 + y.z;
            res[e1][3] = gamma * a3 + y.w;
        }
        int n0 = f * 4;
        int wd = n0 >> 8, hd = (n0 >> 4) & 15, dd0 = n0 & 15;
        int Wn = wd * 4 + wq;
        int Hn = hq + hd;
        size_t oi = obase + (size_t)Wn * 4096 + (size_t)Hn * 64 + dd0 * 4;
#pragma unroll
        for (int nn = 0; nn < 4; nn++) {
            *reinterpret_cast<float4*>(out + oi + nn * 4) =
                make_float4(res[0][nn], res[1][nn], res[2][nn], res[3][nn]);
        }
    }
}

// ---------------- launch ---------------------------------------------------
extern "C" void kernel_launch(void* const* d_in, const int* in_sizes, int n_in,
                              void* d_out, int out_size) {
    const float* x     = (const float*)d_in[0];
    const float* gamma = (const float*)d_in[1];
    float* out = (float*)d_out;

    pack_kernel<<<32768, 256>>>(x);

    cudaFuncSetAttribute(gram_kernel, cudaFuncAttributeMaxDynamicSharedMemorySize, 67584);
    gram_kernel<<<dim3(136, 4), 256, 67584>>>();

    cudaFuncSetAttribute(fuse_kernel, cudaFuncAttributeMaxDynamicSharedMemorySize, 67840);
    fuse_kernel<<<2048, 512, 67840>>>(gamma, out);
}